// round 13
// baseline (speedup 1.0000x reference)
#include <cuda_runtime.h>
#include <cstdint>

// GestureRNN: 2-layer ReLU RNN, B=4096, T=512, IN=10, H=32, NCLS=9.
// R13 = R12 (409us, best) + register diet for occupancy:
//  - x buffering: 40 regs (2x 80B groups) -> 10 regs (one 40B row via
//    5x LDG.64) + prefetch.global.L1 two rows ahead (covers DRAM 577cyc,
//    reload hits L1)
//  - layer-1 accumulators merged: wi1 and wh1 share one 16-deep chain
//    (saves 2 ull regs + 2 fadd2; not on the cross-step critical path)
//  - 64-thread CTAs, __launch_bounds__(64,7) -> target 14 warps/SM vs 12
// Recurrence logic byte-identical to R12 otherwise: 1 syncwarp/step,
// parity double-buffered h1/h2, register-carried w0 partial + xp seeds.

typedef unsigned long long ull;

__device__ __forceinline__ ull ffma2(ull a, ull b, ull c) {
    ull d;
    asm("fma.rn.f32x2 %0, %1, %2, %3;" : "=l"(d) : "l"(a), "l"(b), "l"(c));
    return d;
}
__device__ __forceinline__ ull fadd2(ull a, ull b) {
    ull d;
    asm("add.rn.f32x2 %0, %1, %2;" : "=l"(d) : "l"(a), "l"(b));
    return d;
}
__device__ __forceinline__ float hsum2(ull a) {
    return __uint_as_float((unsigned)a) + __uint_as_float((unsigned)(a >> 32));
}

static constexpr int T_STEPS = 512;
static constexpr int BATCH   = 4096;
static constexpr int IN_DIM  = 10;
static constexpr int NCLS    = 9;
static constexpr int WARPS   = 2;   // 64-thread CTAs

struct __align__(16) WarpBuf {
    float h1[2][32];
    float h2[2][32];
};

__global__ void __launch_bounds__(WARPS * 32, 7) rnn_fused_kernel(
    const float* __restrict__ x,
    const float* __restrict__ Wih0, const float* __restrict__ Whh0,
    const float* __restrict__ bih0, const float* __restrict__ bhh0,
    const float* __restrict__ Wih1, const float* __restrict__ Whh1,
    const float* __restrict__ bih1, const float* __restrict__ bhh1,
    const float* __restrict__ Wfc,  const float* __restrict__ bfc,
    float* __restrict__ out)
{
    __shared__ WarpBuf buf[WARPS];

    const int w   = threadIdx.x >> 5;
    const int lid = threadIdx.x & 31;
    const int b   = blockIdx.x * WARPS + w;
    WarpBuf& wb = buf[w];

    // ---- per-lane weight rows, packed f32x2 over k-pairs ----
    ull w0[16], wi1[16], wh1[16], xw[5];
    {
        const ulonglong2* p0 = (const ulonglong2*)(Whh0 + lid * 32);
        const ulonglong2* p1 = (const ulonglong2*)(Wih1 + lid * 32);
        const ulonglong2* p2 = (const ulonglong2*)(Whh1 + lid * 32);
#pragma unroll
        for (int m = 0; m < 8; m++) {
            ulonglong2 a = p0[m]; w0[2*m]  = a.x; w0[2*m+1]  = a.y;
            ulonglong2 c = p1[m]; wi1[2*m] = c.x; wi1[2*m+1] = c.y;
            ulonglong2 d = p2[m]; wh1[2*m] = d.x; wh1[2*m+1] = d.y;
        }
        const ull* px = (const ull*)(Wih0 + lid * IN_DIM);  // 40B rows, 8B aligned
#pragma unroll
        for (int m = 0; m < 5; m++) xw[m] = px[m];
    }
    const float b0f = bih0[lid] + bhh0[lid];
    const float b1f = bih1[lid] + bhh1[lid];

    wb.h2[0][lid] = 0.f;

    // x rows: row t at 40B stride, 8B aligned -> 5x LDG.64 per row.
    const char* xbase = (const char*)(x + (size_t)b * (T_STEPS * IN_DIM));
    const char* xlast = xbase + (size_t)(T_STEPS - 1) * 40;

    // carry seed for step 0: xw . x_0   (h1_{-1} = 0)
    ull carA, carB;
    {
        const ull* r0 = (const ull*)xbase;
        carA = ffma2(xw[0], r0[0], (ull)0);
        carB = ffma2(xw[1], r0[1], (ull)0);
        carA = ffma2(xw[2], r0[2], carA);
        carB = ffma2(xw[3], r0[3], carB);
        carA = ffma2(xw[4], r0[4], carA);
    }

    // xr = row x_{t+1} (seed source); xnext points at row t+2 for reload
    ull xr[5];
    {
        const ull* r1 = (const ull*)(xbase + 40);
#pragma unroll
        for (int m = 0; m < 5; m++) xr[m] = r1[m];
    }
    const char* xnext = xbase + 80;   // row 2

    // One recurrence step; P = t&1 (compile-time via 2x unroll).
    // Seeds (xw . xr) init the carry chains; xr reloaded right after use.
#define RNN_STEP(P)                                                           \
    {                                                                         \
        const int Q = (P) ^ 1;                                                \
        float h1n = fmaxf(b0f + hsum2(fadd2(carA, carB)), 0.f);               \
        wb.h1[(P)][lid] = h1n;                                                \
        __syncwarp();                                                         \
        ull nA = ffma2(xw[0], xr[0], (ull)0);                                 \
        ull nB = ffma2(xw[1], xr[1], (ull)0);                                 \
        nA = ffma2(xw[2], xr[2], nA);                                         \
        nB = ffma2(xw[3], xr[3], nB);                                         \
        nA = ffma2(xw[4], xr[4], nA);                                         \
        /* reload xr <- row t+2 (L1-resident via prefetch below) */           \
        {                                                                     \
            const ull* rn = (const ull*)xnext;                                \
            xr[0] = rn[0]; xr[1] = rn[1]; xr[2] = rn[2];                      \
            xr[3] = rn[3]; xr[4] = rn[4];                                     \
            const char* xp2 = xnext + 80;  /* prefetch row t+4 */             \
            if (xp2 > xlast) xp2 = xlast;                                     \
            asm volatile("prefetch.global.L1 [%0];" :: "l"(xp2));             \
            xnext += 40;                                                      \
            if (xnext > xlast) xnext = xlast;                                 \
        }                                                                     \
        const ulonglong2* h1p = (const ulonglong2*)wb.h1[(P)];                \
        const ulonglong2* h2p = (const ulonglong2*)wb.h2[(P)];                \
        ull aA = 0ull, aB = 0ull;                                             \
        _Pragma("unroll")                                                     \
        for (int m = 0; m < 8; m++) {                                         \
            ulonglong2 qa = h1p[m];                                           \
            aA = ffma2(wi1[2*m],   qa.x, aA);                                 \
            aB = ffma2(wi1[2*m+1], qa.y, aB);                                 \
            nA = ffma2(w0[2*m],    qa.x, nA);                                 \
            nB = ffma2(w0[2*m+1],  qa.y, nB);                                 \
        }                                                                     \
        _Pragma("unroll")                                                     \
        for (int m = 0; m < 8; m++) {                                         \
            ulonglong2 ra = h2p[m];                                           \
            aA = ffma2(wh1[2*m],   ra.x, aA);                                 \
            aB = ffma2(wh1[2*m+1], ra.y, aB);                                 \
        }                                                                     \
        float h2n = fmaxf(b1f + hsum2(fadd2(aA, aB)), 0.f);                   \
        wb.h2[Q][lid] = h2n;                                                  \
        carA = nA; carB = nB;                                                 \
    }

    for (int gg = 0; gg < T_STEPS / 2; gg++) {
        RNN_STEP(0);   // even t
        RNN_STEP(1);   // odd t
    }
#undef RNN_STEP
    __syncwarp();

    // classifier head: t=511 (P=1) wrote h2 parity 0
    if (lid < NCLS) {
        float o = bfc[lid];
        const float* wr  = Wfc + lid * 32;
        const float* h2f = wb.h2[0];
#pragma unroll
        for (int j = 0; j < 32; j++) o += h2f[j] * wr[j];
        out[(size_t)b * NCLS + lid] = o;
    }
}

extern "C" void kernel_launch(void* const* d_in, const int* in_sizes, int n_in,
                              void* d_out, int out_size)
{
    const float* x    = (const float*)d_in[0];
    const float* Wih0 = (const float*)d_in[1];
    const float* Whh0 = (const float*)d_in[2];
    const float* bih0 = (const float*)d_in[3];
    const float* bhh0 = (const float*)d_in[4];
    const float* Wih1 = (const float*)d_in[5];
    const float* Whh1 = (const float*)d_in[6];
    const float* bih1 = (const float*)d_in[7];
    const float* bhh1 = (const float*)d_in[8];
    const float* Wfc  = (const float*)d_in[9];
    const float* bfc  = (const float*)d_in[10];
    float* out = (float*)d_out;

    rnn_fused_kernel<<<BATCH / WARPS, WARPS * 32>>>(
        x, Wih0, Whh0, bih0, bhh0, Wih1, Whh1, bih1, bhh1, Wfc, bfc, out);
}

// round 14
// speedup vs baseline: 1.0690x; 1.0690x over previous
#include <cuda_runtime.h>
#include <cstdint>

// GestureRNN: 2-layer ReLU RNN, B=4096, T=512, IN=10, H=32, NCLS=9.
// R14 = R12 (409us best) with a register diet that KEEPS the lean loop:
//  - single 80B x-group buffer (20 regs, was 40): step-even seeds from the
//    odd half, reload <- G(g+1) between the two steps (5x LDG.128 per 2
//    steps, same instr count as R12), step-odd seeds from the even half.
//  - layer-1 chains merged (wi1+wh1 share aA/aB): -4 regs, -2 fadd2.
//  - 64-thread CTAs + __launch_bounds__(64,7): <=146 regs -> 14 warps/SM.
// Everything else byte-identical to R12: 1 syncwarp/step, parity
// double-buffered h1/h2, register-carried w0 partial + xp seeds.

typedef unsigned long long ull;

__device__ __forceinline__ ull ffma2(ull a, ull b, ull c) {
    ull d;
    asm("fma.rn.f32x2 %0, %1, %2, %3;" : "=l"(d) : "l"(a), "l"(b), "l"(c));
    return d;
}
__device__ __forceinline__ ull fadd2(ull a, ull b) {
    ull d;
    asm("add.rn.f32x2 %0, %1, %2;" : "=l"(d) : "l"(a), "l"(b));
    return d;
}
__device__ __forceinline__ float hsum2(ull a) {
    return __uint_as_float((unsigned)a) + __uint_as_float((unsigned)(a >> 32));
}

static constexpr int T_STEPS = 512;
static constexpr int BATCH   = 4096;
static constexpr int IN_DIM  = 10;
static constexpr int NCLS    = 9;
static constexpr int WARPS   = 2;   // 64-thread CTAs

struct __align__(16) WarpBuf {
    float h1[2][32];
    float h2[2][32];
};

__global__ void __launch_bounds__(WARPS * 32, 7) rnn_fused_kernel(
    const float* __restrict__ x,
    const float* __restrict__ Wih0, const float* __restrict__ Whh0,
    const float* __restrict__ bih0, const float* __restrict__ bhh0,
    const float* __restrict__ Wih1, const float* __restrict__ Whh1,
    const float* __restrict__ bih1, const float* __restrict__ bhh1,
    const float* __restrict__ Wfc,  const float* __restrict__ bfc,
    float* __restrict__ out)
{
    __shared__ WarpBuf buf[WARPS];

    const int w   = threadIdx.x >> 5;
    const int lid = threadIdx.x & 31;
    const int b   = blockIdx.x * WARPS + w;
    WarpBuf& wb = buf[w];

    // ---- per-lane weight rows, packed f32x2 over k-pairs ----
    ull w0[16], wi1[16], wh1[16], xw[5];
    {
        const ulonglong2* p0 = (const ulonglong2*)(Whh0 + lid * 32);
        const ulonglong2* p1 = (const ulonglong2*)(Wih1 + lid * 32);
        const ulonglong2* p2 = (const ulonglong2*)(Whh1 + lid * 32);
#pragma unroll
        for (int m = 0; m < 8; m++) {
            ulonglong2 a = p0[m]; w0[2*m]  = a.x; w0[2*m+1]  = a.y;
            ulonglong2 c = p1[m]; wi1[2*m] = c.x; wi1[2*m+1] = c.y;
            ulonglong2 d = p2[m]; wh1[2*m] = d.x; wh1[2*m+1] = d.y;
        }
        const ull* px = (const ull*)(Wih0 + lid * IN_DIM);  // 40B rows, 8B aligned
#pragma unroll
        for (int m = 0; m < 5; m++) xw[m] = px[m];
    }
    const float b0f = bih0[lid] + bhh0[lid];
    const float b1f = bih1[lid] + bhh1[lid];

    wb.h2[0][lid] = 0.f;

    // x groups: group g = steps 2g,2g+1 = 80B = 5 x ulonglong2, 16B aligned
    // (batch base 20480B, group stride 80B).
    const ulonglong2* xgp = (const ulonglong2*)(x + (size_t)b * (T_STEPS * IN_DIM));

    ulonglong2 xG[5];
#pragma unroll
    for (int j = 0; j < 5; j++) xG[j] = xgp[j];   // G(0)

    // carry seed for step 0: xw . x_0 (even half of G(0));  h1_{-1} = 0
    ull carA, carB;
    carA = ffma2(xw[0], xG[0].x, (ull)0);
    carB = ffma2(xw[1], xG[0].y, (ull)0);
    carA = ffma2(xw[2], xG[1].x, carA);
    carB = ffma2(xw[3], xG[1].y, carB);
    carA = ffma2(xw[4], xG[2].x, carA);

    // One recurrence step. P = parity (t&1), seeds s0..s4 = packed pairs of
    // x_{t+1} feeding the carry-chain init. Layer-1 uses ONE merged chain
    // pair (aA,aB) across wi1 and wh1.
#define RNN_STEP(P, s0, s1, s2, s3, s4)                                       \
    {                                                                         \
        const int Q = (P) ^ 1;                                                \
        float h1n = fmaxf(b0f + hsum2(fadd2(carA, carB)), 0.f);               \
        wb.h1[(P)][lid] = h1n;                                                \
        __syncwarp();                                                         \
        ull nA = ffma2(xw[0], (s0), (ull)0);                                  \
        ull nB = ffma2(xw[1], (s1), (ull)0);                                  \
        nA = ffma2(xw[2], (s2), nA);                                          \
        nB = ffma2(xw[3], (s3), nB);                                          \
        nA = ffma2(xw[4], (s4), nA);                                          \
        const ulonglong2* h1p = (const ulonglong2*)wb.h1[(P)];                \
        const ulonglong2* h2p = (const ulonglong2*)wb.h2[(P)];                \
        ull aA = 0ull, aB = 0ull;                                             \
        _Pragma("unroll")                                                     \
        for (int m = 0; m < 8; m++) {                                         \
            ulonglong2 qa = h1p[m];                                           \
            aA = ffma2(wi1[2*m],   qa.x, aA);                                 \
            aB = ffma2(wi1[2*m+1], qa.y, aB);                                 \
            nA = ffma2(w0[2*m],    qa.x, nA);                                 \
            nB = ffma2(w0[2*m+1],  qa.y, nB);                                 \
        }                                                                     \
        _Pragma("unroll")                                                     \
        for (int m = 0; m < 8; m++) {                                         \
            ulonglong2 ra = h2p[m];                                           \
            aA = ffma2(wh1[2*m],   ra.x, aA);                                 \
            aB = ffma2(wh1[2*m+1], ra.y, aB);                                 \
        }                                                                     \
        float h2n = fmaxf(b1f + hsum2(fadd2(aA, aB)), 0.f);                   \
        wb.h2[Q][lid] = h2n;                                                  \
        carA = nA; carB = nB;                                                 \
    }

    for (int g = 0; g < T_STEPS / 2; g++) {
        // step 2g (P=0): seed x_{2g+1} = odd half of G(g)
        RNN_STEP(0, xG[2].y, xG[3].x, xG[3].y, xG[4].x, xG[4].y);

        // reload xG <- G(g+1) (clamped; garbage only seeds the dead final carry)
        {
            const int gn = (g + 1 < T_STEPS / 2) ? (g + 1) : (T_STEPS / 2 - 1);
            const ulonglong2* src = xgp + 5 * gn;
#pragma unroll
            for (int j = 0; j < 5; j++) xG[j] = src[j];
        }

        // step 2g+1 (P=1): seed x_{2g+2} = even half of G(g+1)
        RNN_STEP(1, xG[0].x, xG[0].y, xG[1].x, xG[1].y, xG[2].x);
    }
#undef RNN_STEP
    __syncwarp();

    // classifier head: t=511 (P=1) wrote h2 parity 0
    if (lid < NCLS) {
        float o = bfc[lid];
        const float* wr  = Wfc + lid * 32;
        const float* h2f = wb.h2[0];
#pragma unroll
        for (int j = 0; j < 32; j++) o += h2f[j] * wr[j];
        out[(size_t)b * NCLS + lid] = o;
    }
}

extern "C" void kernel_launch(void* const* d_in, const int* in_sizes, int n_in,
                              void* d_out, int out_size)
{
    const float* x    = (const float*)d_in[0];
    const float* Wih0 = (const float*)d_in[1];
    const float* Whh0 = (const float*)d_in[2];
    const float* bih0 = (const float*)d_in[3];
    const float* bhh0 = (const float*)d_in[4];
    const float* Wih1 = (const float*)d_in[5];
    const float* Whh1 = (const float*)d_in[6];
    const float* bih1 = (const float*)d_in[7];
    const float* bhh1 = (const float*)d_in[8];
    const float* Wfc  = (const float*)d_in[9];
    const float* bfc  = (const float*)d_in[10];
    float* out = (float*)d_out;

    rnn_fused_kernel<<<BATCH / WARPS, WARPS * 32>>>(
        x, Wih0, Whh0, bih0, bhh0, Wih1, Whh1, bih1, bhh1, Wfc, bfc, out);
}

// round 15
// speedup vs baseline: 1.3584x; 1.2707x over previous
#include <cuda_runtime.h>
#include <cstdint>

// GestureRNN: 2-layer ReLU RNN, B=4096, T=512, IN=10, H=32, NCLS=9.
// R15 = R12 (409us best, block=128 REQUIRED: 64-thr CTAs only use SMSP 0/1)
// with scheduling polish, structure otherwise identical:
//  - preseed pipeline: P0-step seed ffma2s computed one step early from the
//    single x-group buffer (x regs 40->24); reload->use gap >= 1.2 steps.
//  - biases folded into chain inits (pack2(b,0)) - one FADD off the
//    critical h1n path per step.
//  - carry (n) chain ordered first in the fused block.

typedef unsigned long long ull;

__device__ __forceinline__ ull ffma2(ull a, ull b, ull c) {
    ull d;
    asm("fma.rn.f32x2 %0, %1, %2, %3;" : "=l"(d) : "l"(a), "l"(b), "l"(c));
    return d;
}
__device__ __forceinline__ ull fadd2(ull a, ull b) {
    ull d;
    asm("add.rn.f32x2 %0, %1, %2;" : "=l"(d) : "l"(a), "l"(b));
    return d;
}
__device__ __forceinline__ float hsum2(ull a) {
    return __uint_as_float((unsigned)a) + __uint_as_float((unsigned)(a >> 32));
}
__device__ __forceinline__ ull pack2(float lo, float hi) {
    ull d;
    asm("mov.b64 %0, {%1, %2};" : "=l"(d) : "f"(lo), "f"(hi));
    return d;
}

static constexpr int T_STEPS = 512;
static constexpr int BATCH   = 4096;
static constexpr int IN_DIM  = 10;
static constexpr int NCLS    = 9;
static constexpr int WARPS   = 4;   // 128-thread CTAs (all 4 SMSPs)

struct __align__(16) WarpBuf {
    float h1[2][32];
    float h2[2][32];
};

__global__ void __launch_bounds__(WARPS * 32, 3) rnn_fused_kernel(
    const float* __restrict__ x,
    const float* __restrict__ Wih0, const float* __restrict__ Whh0,
    const float* __restrict__ bih0, const float* __restrict__ bhh0,
    const float* __restrict__ Wih1, const float* __restrict__ Whh1,
    const float* __restrict__ bih1, const float* __restrict__ bhh1,
    const float* __restrict__ Wfc,  const float* __restrict__ bfc,
    float* __restrict__ out)
{
    __shared__ WarpBuf buf[WARPS];

    const int w   = threadIdx.x >> 5;
    const int lid = threadIdx.x & 31;
    const int b   = blockIdx.x * WARPS + w;
    WarpBuf& wb = buf[w];

    // ---- per-lane weight rows, packed f32x2 over k-pairs ----
    ull w0[16], wi1[16], wh1[16], xw[5];
    {
        const ulonglong2* p0 = (const ulonglong2*)(Whh0 + lid * 32);
        const ulonglong2* p1 = (const ulonglong2*)(Wih1 + lid * 32);
        const ulonglong2* p2 = (const ulonglong2*)(Whh1 + lid * 32);
#pragma unroll
        for (int m = 0; m < 8; m++) {
            ulonglong2 a = p0[m]; w0[2*m]  = a.x; w0[2*m+1]  = a.y;
            ulonglong2 c = p1[m]; wi1[2*m] = c.x; wi1[2*m+1] = c.y;
            ulonglong2 d = p2[m]; wh1[2*m] = d.x; wh1[2*m+1] = d.y;
        }
        const ull* px = (const ull*)(Wih0 + lid * IN_DIM);  // 40B rows, 8B aligned
#pragma unroll
        for (int m = 0; m < 5; m++) xw[m] = px[m];
    }
    const ull BIAS0 = pack2(bih0[lid] + bhh0[lid], 0.f);
    const ull BIAS1 = pack2(bih1[lid] + bhh1[lid], 0.f);

    wb.h2[0][lid] = 0.f;

    // x groups: group g = steps 2g,2g+1 = 80B = 5 x ulonglong2, 16B aligned.
    const ulonglong2* xgp = (const ulonglong2*)(x + (size_t)b * (T_STEPS * IN_DIM));

    ulonglong2 xG[5];
#pragma unroll
    for (int j = 0; j < 5; j++) xG[j] = xgp[j];   // G(0)

    // carry for step 0: bias + xw.x_0 (even half of G(0)); h1_{-1} = 0
    ull carA, carB;
    carA = ffma2(xw[0], xG[0].x, BIAS0);
    carB = ffma2(xw[1], xG[0].y, (ull)0);
    carA = ffma2(xw[2], xG[1].x, carA);
    carB = ffma2(xw[3], xG[1].y, carB);
    carA = ffma2(xw[4], xG[2].x, carA);

    // preseed for step 0's n-chain: bias + xw.x_1 (odd half of G(0))
    ull pA, pB;
    pA = ffma2(xw[0], xG[2].y, BIAS0);
    pB = ffma2(xw[1], xG[3].x, (ull)0);
    pA = ffma2(xw[2], xG[3].y, pA);
    pB = ffma2(xw[3], xG[4].x, pB);
    pA = ffma2(xw[4], xG[4].y, pA);

    // xG <- G(1)
#pragma unroll
    for (int j = 0; j < 5; j++) xG[j] = xgp[5 + j];

    const ulonglong2* h1p0 = (const ulonglong2*)wb.h1[0];
    const ulonglong2* h2p0 = (const ulonglong2*)wb.h2[0];
    const ulonglong2* h1p1 = (const ulonglong2*)wb.h1[1];
    const ulonglong2* h2p1 = (const ulonglong2*)wb.h2[1];

    for (int g = 0; g < T_STEPS / 2; g++) {
        // ================= step t=2g (P=0) =================
        {
            float h1n = fmaxf(hsum2(fadd2(carA, carB)), 0.f);
            wb.h1[0][lid] = h1n;
            __syncwarp();
            ull nA = pA, nB = pB;
            ull aA = 0ull, aB = 0ull, cA = BIAS1, cB = 0ull;
#pragma unroll
            for (int m = 0; m < 8; m++) {
                ulonglong2 qa = h1p0[m];
                ulonglong2 ra = h2p0[m];
                nA = ffma2(w0[2*m],    qa.x, nA);
                nB = ffma2(w0[2*m+1],  qa.y, nB);
                aA = ffma2(wi1[2*m],   qa.x, aA);
                aB = ffma2(wi1[2*m+1], qa.y, aB);
                cA = ffma2(wh1[2*m],   ra.x, cA);
                cB = ffma2(wh1[2*m+1], ra.y, cB);
            }
            float h2n = fmaxf(hsum2(fadd2(fadd2(aA, aB), fadd2(cA, cB))), 0.f);
            wb.h2[1][lid] = h2n;
            carA = nA; carB = nB;
        }

        // preseed for step 2g+2: bias + xw.x_{2g+3} (odd half of xG=G(g+1))
        pA = ffma2(xw[0], xG[2].y, BIAS0);
        pB = ffma2(xw[1], xG[3].x, (ull)0);
        pA = ffma2(xw[2], xG[3].y, pA);
        pB = ffma2(xw[3], xG[4].x, pB);
        pA = ffma2(xw[4], xG[4].y, pA);

        // ================= step t=2g+1 (P=1) =================
        {
            float h1n = fmaxf(hsum2(fadd2(carA, carB)), 0.f);
            wb.h1[1][lid] = h1n;
            __syncwarp();
            // seeds inline: bias + xw.x_{2g+2} (even half of xG=G(g+1))
            ull nA = ffma2(xw[0], xG[0].x, BIAS0);
            ull nB = ffma2(xw[1], xG[0].y, (ull)0);
            nA = ffma2(xw[2], xG[1].x, nA);
            nB = ffma2(xw[3], xG[1].y, nB);
            nA = ffma2(xw[4], xG[2].x, nA);
            ull aA = 0ull, aB = 0ull, cA = BIAS1, cB = 0ull;
#pragma unroll
            for (int m = 0; m < 8; m++) {
                ulonglong2 qa = h1p1[m];
                ulonglong2 ra = h2p1[m];
                nA = ffma2(w0[2*m],    qa.x, nA);
                nB = ffma2(w0[2*m+1],  qa.y, nB);
                aA = ffma2(wi1[2*m],   qa.x, aA);
                aB = ffma2(wi1[2*m+1], qa.y, aB);
                cA = ffma2(wh1[2*m],   ra.x, cA);
                cB = ffma2(wh1[2*m+1], ra.y, cB);
            }
            float h2n = fmaxf(hsum2(fadd2(fadd2(aA, aB), fadd2(cA, cB))), 0.f);
            wb.h2[0][lid] = h2n;
            carA = nA; carB = nB;
        }

        // reload xG <- G(g+2) (clamped; garbage feeds only the dead final carry)
        {
            const int gn = (g + 2 < T_STEPS / 2) ? (g + 2) : (T_STEPS / 2 - 1);
            const ulonglong2* src = xgp + 5 * gn;
#pragma unroll
            for (int j = 0; j < 5; j++) xG[j] = src[j];
        }
    }
    __syncwarp();

    // classifier head: t=511 (P=1) wrote h2 parity 0
    if (lid < NCLS) {
        float o = bfc[lid];
        const float* wr  = Wfc + lid * 32;
        const float* h2f = wb.h2[0];
#pragma unroll
        for (int j = 0; j < 32; j++) o += h2f[j] * wr[j];
        out[(size_t)b * NCLS + lid] = o;
    }
}

extern "C" void kernel_launch(void* const* d_in, const int* in_sizes, int n_in,
                              void* d_out, int out_size)
{
    const float* x    = (const float*)d_in[0];
    const float* Wih0 = (const float*)d_in[1];
    const float* Whh0 = (const float*)d_in[2];
    const float* bih0 = (const float*)d_in[3];
    const float* bhh0 = (const float*)d_in[4];
    const float* Wih1 = (const float*)d_in[5];
    const float* Whh1 = (const float*)d_in[6];
    const float* bih1 = (const float*)d_in[7];
    const float* bhh1 = (const float*)d_in[8];
    const float* Wfc  = (const float*)d_in[9];
    const float* bfc  = (const float*)d_in[10];
    float* out = (float*)d_out;

    rnn_fused_kernel<<<BATCH / WARPS, WARPS * 32>>>(
        x, Wih0, Whh0, bih0, bhh0, Wih1, Whh1, bih1, bhh1, Wfc, bfc, out);
}